// round 17
// baseline (speedup 1.0000x reference)
#include <cuda_runtime.h>
#include <cuda_bf16.h>
#include <cstdint>

#define BATCH 2048
#define RPB   16       // rows per MLP CTA (one warp-owned M=16 tile)
#define NCTA  128
#define NTHR  256
#define XCOLS 39
#define HID   128
#define WP    272      // emb smem pitch bytes (136 bf16)
#define HCP   132      // hc/hb smem pitch floats (bank-conflict pad)

// ---- smem byte offsets ----
#define E_H 0          // emb A hi [16][WP]  4352
#define E_L 4352
#define OHC 8704       // hc raw f32 [16][132]  8448
#define OHB 17152      // hb raw f32 [16][132]  8448
#define OW2 25600      // wc2bar [128][8] f32   4096
#define OB1 29696      // bf1 [128]
#define OB2 30208      // bf2
#define OB3 30720      // bc1
#define OB4 31232      // bb1
#define OWB 31744      // Wb2
#define OBC 32256      // bc2bar[6], [6]=bb2 (32B)
#define OSB 32288      // sbase [16] (64B)
#define OPC 32352      // contraction partials [16r][7k][2half] f32 (896B)
#define OCF 33248      // coefB [16][4][4] f32 (1024B)  <-- FIXED: full size, disjoint
#define OIX 34272      // x categorical idx [16][3] int (192B)
#define MLP_SMEM 34464

// weights preconverted into mma.sync B-fragment order:
// idx = ((m*8 + K)*16 + slice)*32 + lane ; uint4 = {bh0, bh1, bl0, bl1}
__device__ uint4 g_bfrag[4 * 8 * 16 * 32];

// ---------------- PTX wrappers ----------------
__device__ __forceinline__ void ldm4(uint32_t r[4], uint32_t a) {
    asm volatile("ldmatrix.sync.aligned.m8n8.x4.shared.b16 {%0,%1,%2,%3}, [%4];"
                 : "=r"(r[0]), "=r"(r[1]), "=r"(r[2]), "=r"(r[3]) : "r"(a));
}
__device__ __forceinline__ void mma_bf16(float d[4], const uint32_t a[4],
                                         uint32_t b0, uint32_t b1) {
    asm("mma.sync.aligned.m16n8k16.row.col.f32.bf16.bf16.f32 "
        "{%0,%1,%2,%3}, {%4,%5,%6,%7}, {%8,%9}, {%0,%1,%2,%3};"
        : "+f"(d[0]), "+f"(d[1]), "+f"(d[2]), "+f"(d[3])
        : "r"(a[0]), "r"(a[1]), "r"(a[2]), "r"(a[3]), "r"(b0), "r"(b1));
}
__device__ __forceinline__ void split2(float v0, float v1, uint32_t& hi, uint32_t& lo) {
    __nv_bfloat162 h = __floats2bfloat162_rn(v0, v1);
    float f0 = __bfloat162float(h.x), f1 = __bfloat162float(h.y);
    __nv_bfloat162 g = __floats2bfloat162_rn(v0 - f0, v1 - f1);
    hi = *reinterpret_cast<uint32_t*>(&h);
    lo = *reinterpret_cast<uint32_t*>(&g);
}
__device__ __forceinline__ void l2_prefetch(const void* p) {
    asm volatile("prefetch.global.L2 [%0];" :: "l"(p));
}

// ---------------- fast convert (R14-verified) ----------------
__global__ __launch_bounds__(256) void convert_kernel(
    const float* __restrict__ Wf1, const float* __restrict__ Wf2,
    const float* __restrict__ Wc1, const float* __restrict__ Wb1)
{
    __shared__ float ws[16][132];
    int b = blockIdx.x;
    int m = b >> 3, K = b & 7;
    int tid = threadIdx.x;
    const float* src = (m == 0) ? Wf1 : (m == 1) ? Wf2 : (m == 2) ? Wc1 : Wb1;

    #pragma unroll
    for (int i = 0; i < 2; i++) {
        int e = tid + i * 256;
        int r = e >> 5, c4 = e & 31;
        int gr = K * 16 + r;
        float4 v = make_float4(0.f, 0.f, 0.f, 0.f);
        if (m != 0 || gr < 68) v = ((const float4*)src)[gr * 32 + c4];
        *(float4*)&ws[r][c4 * 4] = v;
    }
    __syncthreads();

    int lane = tid & 31, s = tid >> 5;
    int ql = lane & 3, gid = lane >> 2;
    int k0 = 2 * ql;
    #pragma unroll
    for (int h = 0; h < 2; h++) {
        int ss = s + h * 8;
        int n = ss * 8 + gid;
        float v0 = ws[k0][n],     v1 = ws[k0 + 1][n];
        float v2 = ws[k0 + 8][n], v3 = ws[k0 + 9][n];
        uint32_t bh0, bl0, bh1, bl1;
        split2(v0, v1, bh0, bl0);
        split2(v2, v3, bh1, bl1);
        g_bfrag[((m * 8 + K) * 16 + ss) * 32 + lane] = make_uint4(bh0, bh1, bl0, bl1);
    }
}

// barrier-free full-width layer: acc[16][4] covers all 128 cols of 16 rows.
// B stream: element i = K*16+s at fr[i*32]; 16-slot ring, prefetch distance 11.
// 3 precision passes staggered by 2 iterations (no back-to-back dependent HMMA).
template<int KS>
__device__ __forceinline__ void mma_chain(float acc[16][4],
                                          const uint32_t ahi[8][4],
                                          const uint32_t alo[8][4],
                                          const uint4* __restrict__ fr)
{
    constexpr int N = KS * 16;
    uint4 ring[16];
    #pragma unroll
    for (int j = 0; j < 11 && j < N; j++) ring[j] = fr[j * 32];
    #pragma unroll
    for (int i = 0; i < N + 4; i++) {
        if (i + 11 < N) ring[(i + 11) & 15] = fr[(i + 11) * 32];
        if (i < N) {
            int s = i & 15, K = i >> 4;
            uint4 B = ring[i & 15];
            mma_bf16(acc[s], ahi[K], B.x, B.y);          // hi*hi
        }
        if (i >= 2 && i < N + 2) {
            int i2 = i - 2;
            int s = i2 & 15, K = i2 >> 4;
            uint4 B = ring[i2 & 15];
            mma_bf16(acc[s], ahi[K], B.z, B.w);          // hi*lo
        }
        if (i >= 4) {
            int i4 = i - 4;
            int s = i4 & 15, K = i4 >> 4;
            uint4 B = ring[i4 & 15];
            mma_bf16(acc[s], alo[K], B.x, B.y);          // lo*hi
        }
    }
}

// C frags -> next-layer A frags (bias+relu), verified in R7
__device__ __forceinline__ void epi_chain(float acc[16][4], const float* __restrict__ bias,
                                          uint32_t ahi[8][4], uint32_t alo[8][4], int ql)
{
    #pragma unroll
    for (int n = 0; n < 16; n++) {
        int c0 = n * 8 + ql * 2;
        float2 b = *(const float2*)(bias + c0);
        float v0 = fmaxf(acc[n][0] + b.x, 0.f);
        float v1 = fmaxf(acc[n][1] + b.y, 0.f);
        float v2 = fmaxf(acc[n][2] + b.x, 0.f);
        float v3 = fmaxf(acc[n][3] + b.y, 0.f);
        int K = n >> 1, h = (n & 1) * 2;
        split2(v0, v1, ahi[K][h],     alo[K][h]);
        split2(v2, v3, ahi[K][h + 1], alo[K][h + 1]);
        acc[n][0] = acc[n][1] = acc[n][2] = acc[n][3] = 0.f;
    }
}

// dump raw accumulators to smem buffer [16][HCP] and reset
__device__ __forceinline__ void dump_acc(float acc[16][4], float* __restrict__ dst,
                                         int r0, int ql)
{
    #pragma unroll
    for (int n = 0; n < 16; n++) {
        int c = n * 8 + ql * 2;
        *(float2*)(dst + r0 * HCP + c)       = make_float2(acc[n][0], acc[n][1]);
        *(float2*)(dst + (r0 + 8) * HCP + c) = make_float2(acc[n][2], acc[n][3]);
        acc[n][0] = acc[n][1] = acc[n][2] = acc[n][3] = 0.f;
    }
}

__global__ __launch_bounds__(NTHR, 1) void mlp_kernel(
    const float* __restrict__ x,
    const float* __restrict__ budget,
    const float* __restrict__ emb_id, const float* __restrict__ emb_period,
    const float* __restrict__ emb_time,
    const float* __restrict__ bf1, const float* __restrict__ bf2,
    const float* __restrict__ bc1, const float* __restrict__ Wc2,
    const float* __restrict__ bc2,
    const float* __restrict__ bb1, const float* __restrict__ Wb2,
    const float* __restrict__ bb2,
    float* __restrict__ out)
{
    extern __shared__ char smem[];
    float* smf = (float*)smem;
    const int tid  = threadIdx.x;
    const int w    = tid >> 5;
    const int lane = tid & 31;
    const int lr   = lane & 15;
    const int lc   = (lane >> 4) * 8;
    const int r0l  = lane >> 2;
    const int ql   = lane & 3;
    const int row0 = blockIdx.x * RPB;
    const uint32_t smb = (uint32_t)__cvta_generic_to_shared(smem);

    // ======== PDL-independent prologue ========
    if (tid < 48) {
        int r = tid / 3, c = tid - r * 3;
        ((int*)(smem + OIX))[r * 3 + c] = (int)x[(row0 + r) * XCOLS + c];
    }
    // L2-prefetch this CTA's 32KB budget slice (one 128B line per thread, no regs)
    l2_prefetch((const char*)budget + (size_t)row0 * 512 * 4 + tid * 128);

    // zero E hi/lo (8704B = 544 uint4)
    #pragma unroll
    for (int i = 0; i < 3; i++) {
        int idx = tid + i * NTHR;
        if (idx < 544) ((uint4*)(smem + E_H))[idx] = make_uint4(0, 0, 0, 0);
    }

    // wc2bar (tid<128) and biases (tid 128..255)
    if (tid < 128) {
        float s[6] = {0, 0, 0, 0, 0, 0};
        const float4* w4 = (const float4*)(Wc2 + tid * 48);
        #pragma unroll
        for (int v = 0; v < 12; v++) {
            float4 f = w4[v];
            s[(v * 4 + 0) % 6] += f.x; s[(v * 4 + 1) % 6] += f.y;
            s[(v * 4 + 2) % 6] += f.z; s[(v * 4 + 3) % 6] += f.w;
        }
        #pragma unroll
        for (int k = 0; k < 6; k++) smf[OW2 / 4 + tid * 8 + k] = s[k] * 0.125f;
        smf[OW2 / 4 + tid * 8 + 6] = 0.f; smf[OW2 / 4 + tid * 8 + 7] = 0.f;
    } else {
        int t = tid - 128;
        smf[OB1 / 4 + t] = bf1[t];
        smf[OB2 / 4 + t] = bf2[t];
        smf[OB3 / 4 + t] = bc1[t];
        smf[OB4 / 4 + t] = bb1[t];
        smf[OWB / 4 + t] = Wb2[t];
        if (t < 6) {
            float s = 0.f;
            #pragma unroll
            for (int j = 0; j < 8; j++) s += bc2[j * 6 + t];
            smf[OBC / 4 + t] = s * 0.125f;
        } else if (t == 6) {
            smf[OBC / 4 + 6] = bb2[0];
        }
    }
    __syncthreads();   // E zeros + OIX visible

    // emb fill: 16 rows x 68 cols, 16 threads/row
    {
        const int* ix = (const int*)(smem + OIX);
        int r = tid >> 4, t16 = tid & 15;
        int i0 = ix[r * 3 + 0], i1 = ix[r * 3 + 1], i2 = ix[r * 3 + 2];
        #pragma unroll
        for (int jj = 0; jj < 5; jj++) {
            int c = t16 + jj * 16;
            if (c < 68) {
                float v;
                if      (c < 8)  v = emb_id    [i1 * 8  + c];
                else if (c < 16) v = emb_period[i0 * 8  + (c - 8)];
                else if (c < 32) v = emb_time  [i2 * 16 + (c - 16)];
                else             v = x[(row0 + r) * XCOLS + 3 + (c - 32)];
                __nv_bfloat16 h = __float2bfloat16(v);
                __nv_bfloat16 l = __float2bfloat16(v - __bfloat162float(h));
                *(__nv_bfloat16*)(smem + E_H + r * WP + c * 2) = h;
                *(__nv_bfloat16*)(smem + E_L + r * WP + c * 2) = l;
            }
        }
    }
    __syncthreads();   // emb + tables visible

    // ======== wait for fragment weights ========
    cudaGridDependencySynchronize();

    // ======== warp 0: barrier-free 4-layer chain over this CTA's 16 rows ========
    if (w == 0) {
        float acc[16][4];
        #pragma unroll
        for (int n = 0; n < 16; n++)
            acc[n][0] = acc[n][1] = acc[n][2] = acc[n][3] = 0.f;
        uint32_t ahi[8][4], alo[8][4];

        // A frags from emb smem (5 ksteps; cols 68..79 zero)
        {
            uint32_t base = smb + E_H + lr * WP + lc * 2;
            uint32_t baseL = smb + E_L + lr * WP + lc * 2;
            #pragma unroll
            for (int K = 0; K < 5; K++) {
                ldm4(ahi[K], base + K * 32);
                ldm4(alo[K], baseL + K * 32);
            }
        }
        const uint4* fr = g_bfrag + lane;

        mma_chain<5>(acc, ahi, alo, fr);                 // L1
        epi_chain(acc, smf + OB1 / 4, ahi, alo, ql);     // h1 -> A frags

        mma_chain<8>(acc, ahi, alo, fr + 4096);          // L2
        epi_chain(acc, smf + OB2 / 4, ahi, alo, ql);     // h2 -> A frags

        mma_chain<8>(acc, ahi, alo, fr + 2 * 4096);      // L3 (hc raw)
        dump_acc(acc, smf + OHC / 4, r0l, ql);

        mma_chain<8>(acc, ahi, alo, fr + 3 * 4096);      // L4 (hb raw; same A frags)
        dump_acc(acc, smf + OHB / 4, r0l, ql);
    }
    __syncthreads();   // hc/hb visible

    // ======== contractions: (r 16) x (k 7) x (half 2) = 224 tasks ========
    {
        int r = tid >> 4, q = tid & 15;
        if (q < 14) {
            int k = q >> 1, half = q & 1;
            float s = 0.f;
            if (k < 6) {
                const float* hc = smf + OHC / 4 + r * HCP + half * 64;
                const float* bc = smf + OB3 / 4 + half * 64;
                const float* wz = smf + OW2 / 4 + half * 64 * 8 + k;
                #pragma unroll 8
                for (int i = 0; i < 64; i++)
                    s += fmaxf(hc[i] + bc[i], 0.f) * wz[i * 8];
            } else {
                const float* hb = smf + OHB / 4 + r * HCP + half * 64;
                const float* bb = smf + OB4 / 4 + half * 64;
                const float* wb = smf + OWB / 4 + half * 64;
                #pragma unroll 8
                for (int i = 0; i < 64; i++)
                    s += fmaxf(hb[i] + bb[i], 0.f) * wb[i];
            }
            smf[OPC / 4 + (r * 7 + k) * 2 + half] = s;
        }
    }
    __syncthreads();

    // ======== cubic (48 threads) + sbase (16 threads) — OCF now disjoint ========
    if (tid < 48) {
        int rb = tid / 3, m = tid - rb * 3;
        float cb[4];
        #pragma unroll
        for (int j = 0; j < 4; j++) {
            const float* p = smf + OPC / 4 + (rb * 7 + m + j) * 2;
            cb[j] = p[0] + p[1] + smf[OBC / 4 + m + j];
        }
        float c0 = cb[0], c1 = cb[1], c2 = cb[2], c3 = cb[3];
        const float k6 = 1.f / 6.f;
        float A0 = (c0 + 4.f * c1 + c2) * k6;
        float A1 = (c2 - c0) * 0.5f;
        float A2 = (c0 - 2.f * c1 + c2) * 0.5f;
        float A3 = (c3 - c0 + 3.f * (c1 - c2)) * k6;
        float d  = 1.5f - (float)m;
        float B0 = A0 + d * (A1 + d * (A2 + d * A3));
        float B1 = 1.5f * (A1 + d * (2.f * A2 + 3.f * A3 * d));
        float B2 = 2.25f * (A2 + 3.f * A3 * d);
        float B3 = 3.375f * A3;
        ((float4*)(smem + OCF))[rb * 4 + m] = make_float4(B0, B1, B2, B3);
    } else if (tid < 64) {
        int rb = tid - 48;
        const float* p = smf + OPC / 4 + (rb * 7 + 6) * 2;
        smf[OSB / 4 + rb] = p[0] + p[1] + smf[OBC / 4 + 6];
    }
    __syncthreads();

    // ======== budget phase: loads hit L2 (prefetched in prologue) ========
    const float4* bud4 = (const float4*)budget + row0 * 128;
    float4* out4 = (float4*)out + row0 * 128;
    const float4* cb4 = (const float4*)(smem + OCF);
    #pragma unroll
    for (int it = 0; it < 8; it++) {
        int q = tid + it * NTHR;
        int row = q >> 7;
        float4 bv = bud4[q];
        float sb = smf[OSB / 4 + row];
        float xs[4] = {bv.x, bv.y, bv.z, bv.w};
        float o[4];
        #pragma unroll
        for (int e = 0; e < 4; e++) {
            float X = xs[e];
            float tp = fmaf(X, 1.5f, 1.5f);
            int m = min((int)tp, 2);
            float4 B = cb4[row * 4 + m];
            float sp = fmaf(fmaf(fmaf(B.w, X, B.z), X, B.y), X, B.x);
            float u = X * X;
            float P = fmaf(u, fmaf(u, fmaf(u, fmaf(u, 2.1357286e-5f, -2.1081349e-4f),
                                           2.0833333e-3f), -2.0833333e-2f), 0.25f);
            float sil = X * fmaf(X, P, 0.5f);
            o[e] = sb * (sil + sp);
        }
        out4[q] = make_float4(o[0], o[1], o[2], o[3]);
    }
}

extern "C" void kernel_launch(void* const* d_in, const int* in_sizes, int n_in,
                              void* d_out, int out_size)
{
    const float* x          = (const float*)d_in[0];
    const float* budget     = (const float*)d_in[1];
    const float* emb_id     = (const float*)d_in[2];
    const float* emb_period = (const float*)d_in[3];
    const float* emb_time   = (const float*)d_in[4];
    const float* Wf1 = (const float*)d_in[5];
    const float* bf1 = (const float*)d_in[6];
    const float* Wf2 = (const float*)d_in[7];
    const float* bf2 = (const float*)d_in[8];
    const float* Wc1 = (const float*)d_in[9];
    const float* bc1 = (const float*)d_in[10];
    const float* Wc2 = (const float*)d_in[11];
    const float* bc2 = (const float*)d_in[12];
    // d_in[13..16] = Ws1/bs1/Ws2/bs2 : unused in reference output
    const float* Wb1 = (const float*)d_in[17];
    const float* bb1 = (const float*)d_in[18];
    const float* Wb2 = (const float*)d_in[19];
    const float* bb2 = (const float*)d_in[20];

    cudaFuncSetAttribute(mlp_kernel, cudaFuncAttributeMaxDynamicSharedMemorySize, MLP_SMEM);

    convert_kernel<<<32, 256>>>(Wf1, Wf2, Wc1, Wb1);

    cudaLaunchConfig_t cfg = {};
    cfg.gridDim = dim3(NCTA);
    cfg.blockDim = dim3(NTHR);
    cfg.dynamicSmemBytes = MLP_SMEM;
    cfg.stream = 0;
    cudaLaunchAttribute attrs[1];
    attrs[0].id = cudaLaunchAttributeProgrammaticStreamSerialization;
    attrs[0].val.programmaticStreamSerializationAllowed = 1;
    cfg.attrs = attrs;
    cfg.numAttrs = 1;
    cudaLaunchKernelEx(&cfg, mlp_kernel,
                       x, budget, emb_id, emb_period, emb_time,
                       bf1, bf2, bc1, Wc2, bc2, bb1, Wb2, bb2, (float*)d_out);
}